// round 13
// baseline (speedup 1.0000x reference)
#include <cuda_runtime.h>
#include <cuda_bf16.h>
#include <cstdint>

// ============================================================================
// DeformableCurrents: E = sum_{p,q} (w_p.w_q) / (1 + |c_p - c_q|^2)
// over combined src/tar set; f symmetric => triangular tiles (x2 off-diag).
//
// v13 (on the working v12 HMMA scheme):
//   - 512x512 triangular tiles: 528 blocks x 64 inner iters (4x amortization
//     of staging + reduction vs v12's 2080 x 32)
//   - B features stored PERMUTED [w0,w4,w1,w5,w2,w6,w3,w7] so each thread's
//     fragment pair (tig, tig+4) is one conflict-free LDS.64
//   - 4 i-strips per warp share each j-fragment + wj load
//   Denominator via mma.sync.m16n8k16.bf16 split-bf16 (validated: 8.7e-6).
//   Epilogue: rcp + 3-fma g-vector; weights fp32.
// ============================================================================

typedef unsigned int u32;

#define THREADS 256
#define G       512          // square tile edge (points)
#define NS      4            // i-strips per warp (G/128)
#define MAX_PTS 24576

__device__ u32    g_FA[8 * MAX_PTS];   // A features: 8 u32 (bf16x2) per point
__device__ uint2  g_FB2[4 * MAX_PTS];  // B features, permuted pairs
__device__ float4 g_W[MAX_PTS];        // weights
__device__ double g_partials[4096];
__device__ unsigned int g_done = 0;

__device__ __forceinline__ float rcpf(float x) {
    float r; asm("rcp.approx.ftz.f32 %0, %1;" : "=f"(r) : "f"(x));
    return r;
}

// D(16x8,f32) = A(16x16,bf16) * B(16x8,bf16)
__device__ __forceinline__ void mma_bf16(
    float& c0, float& c1, float& c2, float& c3,
    u32 a0, u32 a1, u32 a2, u32 a3, u32 b0, u32 b1)
{
    float z = 0.f;
    asm volatile(
        "mma.sync.aligned.m16n8k16.row.col.f32.bf16.bf16.f32 "
        "{%0,%1,%2,%3}, {%4,%5,%6,%7}, {%8,%9}, {%10,%11,%12,%13};"
        : "=f"(c0), "=f"(c1), "=f"(c2), "=f"(c3)
        : "r"(a0), "r"(a1), "r"(a2), "r"(a3), "r"(b0), "r"(b1),
          "f"(z), "f"(z), "f"(z), "f"(z));
}

// ---- per-point geometry ------------------------------------------------------
__device__ __forceinline__ void make_point(
    int t, int N, int M,
    const float* __restrict__ verts, const float* __restrict__ tnorm,
    const float* __restrict__ tcent, const int* __restrict__ sidx,
    float& cx, float& cy, float& cz, float& a2,
    float& wx, float& wy, float& wz)
{
    cx = 0.f; cy = 0.f; cz = 0.f; wx = 0.f; wy = 0.f; wz = 0.f;
    if (t < N) {
        int i0 = sidx[3 * t + 0], i1 = sidx[3 * t + 1], i2 = sidx[3 * t + 2];
        float ax = verts[3 * i0], ay = verts[3 * i0 + 1], az = verts[3 * i0 + 2];
        float bx = verts[3 * i1], by = verts[3 * i1 + 1], bz = verts[3 * i1 + 2];
        float gx = verts[3 * i2], gy = verts[3 * i2 + 1], gz = verts[3 * i2 + 2];
        float e1x = ax - bx, e1y = ay - by, e1z = az - bz;
        float e2x = gx - bx, e2y = gy - by, e2z = gz - bz;
        wx = 0.5f * (e1y * e2z - e1z * e2y);
        wy = 0.5f * (e1z * e2x - e1x * e2z);
        wz = 0.5f * (e1x * e2y - e1y * e2x);
        cx = (ax + bx + gx) * (1.0f / 3.0f);
        cy = (ay + by + gy) * (1.0f / 3.0f);
        cz = (az + bz + gz) * (1.0f / 3.0f);
    } else if (t < N + M) {
        int j = t - N;
        cx = tcent[3 * j];  cy = tcent[3 * j + 1];  cz = tcent[3 * j + 2];
        wx = -tnorm[3 * j]; wy = -tnorm[3 * j + 1]; wz = -tnorm[3 * j + 2];
    }
    a2 = cx * cx + cy * cy + cz * cz;
}

__device__ __forceinline__ unsigned short bfb(float x) {
    __nv_bfloat16 h = __float2bfloat16(x);
    return *(unsigned short*)&h;
}
__device__ __forceinline__ float bff(unsigned short b) {
    __nv_bfloat16 h = *(__nv_bfloat16*)&b;
    return __bfloat162float(h);
}
__device__ __forceinline__ u32 pk(unsigned short lo, unsigned short hi) {
    return (u32)lo | ((u32)hi << 16);
}

// ---- prep: split-bf16 feature vectors + weights --------------------------------
__global__ void prep_kernel(const float* __restrict__ verts,
                            const float* __restrict__ tnorm,
                            const float* __restrict__ tcent,
                            const int*   __restrict__ sidx,
                            int N, int M, int total_pad)
{
    int p = blockIdx.x * blockDim.x + threadIdx.x;
    if (p >= total_pad) return;
    float cx, cy, cz, a2, wx, wy, wz;
    make_point(p, N, M, verts, tnorm, tcent, sidx, cx, cy, cz, a2, wx, wy, wz);

    unsigned short hx = bfb(cx), hy = bfb(cy), hz = bfb(cz);
    float hxf = bff(hx), hyf = bff(hy), hzf = bff(hz);
    unsigned short lx = bfb(cx - hxf), ly = bfb(cy - hyf), lz = bfb(cz - hzf);
    unsigned short m2hx = bfb(-2.f * hxf), m2hy = bfb(-2.f * hyf), m2hz = bfb(-2.f * hzf);
    unsigned short m2lx = bfb(-2.f * bff(lx)), m2ly = bfb(-2.f * bff(ly)), m2lz = bfb(-2.f * bff(lz));
    unsigned short ah = bfb(a2), al = bfb(a2 - bff(ah));
    float b = 1.f + a2;
    unsigned short bh = bfb(b), bl = bfb(b - bff(bh));
    unsigned short one = bfb(1.f), zz = 0;

    // A (row-major K=16): [-2hx,-2hy,-2hz,-2lx,-2ly,-2lz,-2hx,-2hy,-2hz,ah,al,1,1,0,0,0]
    u32* A = &g_FA[8 * p];
    A[0] = pk(m2hx, m2hy); A[1] = pk(m2hz, m2lx);
    A[2] = pk(m2ly, m2lz); A[3] = pk(m2hx, m2hy);
    A[4] = pk(m2hz, ah);   A[5] = pk(al, one);
    A[6] = pk(one, zz);    A[7] = 0;

    // B words (col-major K=16): [hx,hy,hz,hx,hy,hz,lx,ly,lz,1,1,bh,bl,0,0,0]
    u32 B[8];
    B[0] = pk(hx, hy);  B[1] = pk(hz, hx);
    B[2] = pk(hy, hz);  B[3] = pk(lx, ly);
    B[4] = pk(lz, one); B[5] = pk(one, bh);
    B[6] = pk(bl, zz);  B[7] = 0;
    // permuted pairs: thread fragment (tig, tig+4) contiguous
    uint2* BP = &g_FB2[4 * p];
#pragma unroll
    for (int k = 0; k < 4; k++) BP[k] = make_uint2(B[k], B[k + 4]);

    g_W[p] = make_float4(wx, wy, wz, 0.f);
}

// ---- main kernel: 512x512 triangular tiles, HMMA denominators ------------------
__global__ __launch_bounds__(THREADS)
void mma_kernel(int T, int nBlocks, float* __restrict__ out)
{
    __shared__ uint2  sFB[G * 4];     // 16 KB: permuted B features, j-tile
    __shared__ float4 sWj[G];         // 8 KB
    __shared__ float4 sWi[G];         // 8 KB
    __shared__ double rbuf[THREADS];  // 2 KB
    __shared__ int s_last;

    const int tid = threadIdx.x;
    const int wid = tid >> 5;
    const int lid = tid & 31;
    const int gid = lid >> 2;     // groupID 0..7
    const int tig = lid & 3;      // thread-in-group 0..3

    // block -> (ti, tj) triangular
    int b = blockIdx.x, ti = 0, row = T;
    while (b >= row) { b -= row; ti++; row--; }
    const int tj = ti + b;
    const double scale = (ti == tj) ? 1.0 : 2.0;
    const int Ibase = ti * G;
    const int Jbase = tj * G;

    // stage j-tile features + weights, i weights
    {
        const uint4* src = (const uint4*)&g_FB2[Jbase * 4];
        uint4* dst = (uint4*)sFB;
        for (int k = tid; k < G * 2; k += THREADS) dst[k] = src[k];
        for (int k = tid; k < G; k += THREADS) {
            sWj[k] = g_W[Jbase + k];
            sWi[k] = g_W[Ibase + k];
        }
    }

    // A fragments: NS strips of 16 rows per warp
    u32 a[NS][4];
#pragma unroll
    for (int s = 0; s < NS; s++) {
        int r0 = Ibase + s * 128 + wid * 16 + gid;
        int r1 = r0 + 8;
        a[s][0] = g_FA[r0 * 8 + tig];
        a[s][1] = g_FA[r1 * 8 + tig];
        a[s][2] = g_FA[r0 * 8 + tig + 4];
        a[s][3] = g_FA[r1 * 8 + tig + 4];
    }
    __syncthreads();

    // g-vector accumulators: [strip][row-half]{x,y,z}
    float gx[NS][2], gy[NS][2], gz[NS][2];
#pragma unroll
    for (int s = 0; s < NS; s++)
#pragma unroll
        for (int h = 0; h < 2; h++) { gx[s][h] = 0.f; gy[s][h] = 0.f; gz[s][h] = 0.f; }

#pragma unroll 2
    for (int jt = 0; jt < G / 8; jt++) {           // 64 j-subtiles of 8 cols
        const uint2 bf = sFB[(jt * 8 + gid) * 4 + tig];   // conflict-free LDS.64
        const int n0 = jt * 8 + 2 * tig;
        const float4 wj0 = sWj[n0];
        const float4 wj1 = sWj[n0 + 1];

#pragma unroll
        for (int s = 0; s < NS; s++) {
            float c0, c1, c2, c3;
            mma_bf16(c0, c1, c2, c3, a[s][0], a[s][1], a[s][2], a[s][3],
                     bf.x, bf.y);
            float r00 = rcpf(c0), r01 = rcpf(c1), r10 = rcpf(c2), r11 = rcpf(c3);
            gx[s][0] = fmaf(wj0.x, r00, gx[s][0]); gx[s][0] = fmaf(wj1.x, r01, gx[s][0]);
            gy[s][0] = fmaf(wj0.y, r00, gy[s][0]); gy[s][0] = fmaf(wj1.y, r01, gy[s][0]);
            gz[s][0] = fmaf(wj0.z, r00, gz[s][0]); gz[s][0] = fmaf(wj1.z, r01, gz[s][0]);
            gx[s][1] = fmaf(wj0.x, r10, gx[s][1]); gx[s][1] = fmaf(wj1.x, r11, gx[s][1]);
            gy[s][1] = fmaf(wj0.y, r10, gy[s][1]); gy[s][1] = fmaf(wj1.y, r11, gy[s][1]);
            gz[s][1] = fmaf(wj0.z, r10, gz[s][1]); gz[s][1] = fmaf(wj1.z, r11, gz[s][1]);
        }
    }

    // final dot with i-weights
    double e = 0.0;
#pragma unroll
    for (int s = 0; s < NS; s++) {
        int r = s * 128 + wid * 16 + gid;
        float4 wiA = sWi[r], wiB = sWi[r + 8];
        e += (double)(wiA.x * gx[s][0] + wiA.y * gy[s][0] + wiA.z * gz[s][0]);
        e += (double)(wiB.x * gx[s][1] + wiB.y * gy[s][1] + wiB.z * gz[s][1]);
    }

    // deterministic block reduction
    rbuf[tid] = e * scale;
    __syncthreads();
#pragma unroll
    for (int off = THREADS / 2; off > 0; off >>= 1) {
        if (tid < off) rbuf[tid] += rbuf[tid + off];
        __syncthreads();
    }
    if (tid == 0) {
        g_partials[blockIdx.x] = rbuf[0];
        __threadfence();
        unsigned int ticket = atomicAdd(&g_done, 1u);
        s_last = (ticket == (unsigned int)(nBlocks - 1)) ? 1 : 0;
    }
    __syncthreads();

    // last block: fixed-order deterministic final reduction
    if (s_last) {
        double fs = 0.0;
        for (int k = tid; k < nBlocks; k += THREADS)
            fs += g_partials[k];
        rbuf[tid] = fs;
        __syncthreads();
#pragma unroll
        for (int off = THREADS / 2; off > 0; off >>= 1) {
            if (tid < off) rbuf[tid] += rbuf[tid + off];
            __syncthreads();
        }
        if (tid == 0) {
            out[0] = (float)rbuf[0];
            g_done = 0;   // self-restore for next graph replay
        }
    }
}

// ----------------------------------------------------------------------------
extern "C" void kernel_launch(void* const* d_in, const int* in_sizes, int n_in,
                              void* d_out, int out_size)
{
    const float* verts = (const float*)d_in[0];   // src_vertices  (V,3)
    const float* tnorm = (const float*)d_in[1];   // tar_normals   (M,3)
    const float* tcent = (const float*)d_in[2];   // tar_centers   (M,3)
    const int*   sidx  = (const int*)  d_in[3];   // src_indices   (N,3)

    const int N = in_sizes[3] / 3;
    const int M = in_sizes[1] / 3;
    const int total = N + M;
    const int total_pad = ((total + G - 1) / G) * G;
    const int T = total_pad / G;                  // 32 for 16384 points

    prep_kernel<<<(total_pad + 255) / 256, 256>>>(verts, tnorm, tcent, sidx,
                                                  N, M, total_pad);

    const int nBlocks = T * (T + 1) / 2;          // 528
    mma_kernel<<<nBlocks, THREADS>>>(T, nBlocks, (float*)d_out);
}

// round 14
// speedup vs baseline: 1.6007x; 1.6007x over previous
#include <cuda_runtime.h>
#include <cuda_bf16.h>
#include <cstdint>

// ============================================================================
// DeformableCurrents: E = sum_{p,q} (w_p.w_q) / (1 + |c_p - c_q|^2)
// over combined src/tar set; f symmetric => triangular tiles (x2 off-diag).
//
// v14 (v12 structure, G=256, high occupancy) + BOTH matrices on tensor cores:
//   denom D_ij = 1 + d2 : split-bf16 K=16 MMA  (validated, 8.7e-6)
//   dot   W_ij = wi.wj  : split-bf16 K=16 MMA  (hh' + hl' + lh', drop ll')
//   Epilogue per pair: acc += W * rcp(D)   -- 1 MUFU + 1 FMA only.
//   B fragments permuted [w_k, w_{k+4}] -> single conflict-free LDS.64.
//   MUFU (1 rcp/pair) is the floor: ~57.5k cyc ~= 30us.
// ============================================================================

typedef unsigned int u32;

#define THREADS 256
#define G       256          // square tile edge (points)
#define MAX_PTS 20480

__device__ u32    g_FAd[8 * MAX_PTS];   // A features, denominator
__device__ uint2  g_FBd[4 * MAX_PTS];   // B features, denominator (permuted)
__device__ u32    g_FAn[8 * MAX_PTS];   // A features, numerator (weights)
__device__ uint2  g_FBn[4 * MAX_PTS];   // B features, numerator (permuted)
__device__ double g_partials[4096];
__device__ unsigned int g_done = 0;

__device__ __forceinline__ float rcpf(float x) {
    float r; asm("rcp.approx.ftz.f32 %0, %1;" : "=f"(r) : "f"(x));
    return r;
}

// D(16x8,f32) = A(16x16,bf16) * B(16x8,bf16)
__device__ __forceinline__ void mma_bf16(
    float& c0, float& c1, float& c2, float& c3,
    u32 a0, u32 a1, u32 a2, u32 a3, u32 b0, u32 b1)
{
    float z = 0.f;
    asm volatile(
        "mma.sync.aligned.m16n8k16.row.col.f32.bf16.bf16.f32 "
        "{%0,%1,%2,%3}, {%4,%5,%6,%7}, {%8,%9}, {%10,%11,%12,%13};"
        : "=f"(c0), "=f"(c1), "=f"(c2), "=f"(c3)
        : "r"(a0), "r"(a1), "r"(a2), "r"(a3), "r"(b0), "r"(b1),
          "f"(z), "f"(z), "f"(z), "f"(z));
}

// ---- per-point geometry ------------------------------------------------------
__device__ __forceinline__ void make_point(
    int t, int N, int M,
    const float* __restrict__ verts, const float* __restrict__ tnorm,
    const float* __restrict__ tcent, const int* __restrict__ sidx,
    float& cx, float& cy, float& cz, float& a2,
    float& wx, float& wy, float& wz)
{
    cx = 0.f; cy = 0.f; cz = 0.f; wx = 0.f; wy = 0.f; wz = 0.f;
    if (t < N) {
        int i0 = sidx[3 * t + 0], i1 = sidx[3 * t + 1], i2 = sidx[3 * t + 2];
        float ax = verts[3 * i0], ay = verts[3 * i0 + 1], az = verts[3 * i0 + 2];
        float bx = verts[3 * i1], by = verts[3 * i1 + 1], bz = verts[3 * i1 + 2];
        float gx = verts[3 * i2], gy = verts[3 * i2 + 1], gz = verts[3 * i2 + 2];
        float e1x = ax - bx, e1y = ay - by, e1z = az - bz;
        float e2x = gx - bx, e2y = gy - by, e2z = gz - bz;
        wx = 0.5f * (e1y * e2z - e1z * e2y);
        wy = 0.5f * (e1z * e2x - e1x * e2z);
        wz = 0.5f * (e1x * e2y - e1y * e2x);
        cx = (ax + bx + gx) * (1.0f / 3.0f);
        cy = (ay + by + gy) * (1.0f / 3.0f);
        cz = (az + bz + gz) * (1.0f / 3.0f);
    } else if (t < N + M) {
        int j = t - N;
        cx = tcent[3 * j];  cy = tcent[3 * j + 1];  cz = tcent[3 * j + 2];
        wx = -tnorm[3 * j]; wy = -tnorm[3 * j + 1]; wz = -tnorm[3 * j + 2];
    }
    a2 = cx * cx + cy * cy + cz * cz;
}

__device__ __forceinline__ unsigned short bfb(float x) {
    __nv_bfloat16 h = __float2bfloat16(x);
    return *(unsigned short*)&h;
}
__device__ __forceinline__ float bff(unsigned short b) {
    __nv_bfloat16 h = *(__nv_bfloat16*)&b;
    return __bfloat162float(h);
}
__device__ __forceinline__ u32 pk(unsigned short lo, unsigned short hi) {
    return (u32)lo | ((u32)hi << 16);
}

// ---- prep: split-bf16 feature vectors for BOTH GEMMs ---------------------------
__global__ void prep_kernel(const float* __restrict__ verts,
                            const float* __restrict__ tnorm,
                            const float* __restrict__ tcent,
                            const int*   __restrict__ sidx,
                            int N, int M, int total_pad)
{
    int p = blockIdx.x * blockDim.x + threadIdx.x;
    if (p >= total_pad) return;
    float cx, cy, cz, a2, wx, wy, wz;
    make_point(p, N, M, verts, tnorm, tcent, sidx, cx, cy, cz, a2, wx, wy, wz);

    // ----- denominator features -----
    unsigned short hx = bfb(cx), hy = bfb(cy), hz = bfb(cz);
    float hxf = bff(hx), hyf = bff(hy), hzf = bff(hz);
    unsigned short lx = bfb(cx - hxf), ly = bfb(cy - hyf), lz = bfb(cz - hzf);
    unsigned short m2hx = bfb(-2.f * hxf), m2hy = bfb(-2.f * hyf), m2hz = bfb(-2.f * hzf);
    unsigned short m2lx = bfb(-2.f * bff(lx)), m2ly = bfb(-2.f * bff(ly)), m2lz = bfb(-2.f * bff(lz));
    unsigned short ah = bfb(a2), al = bfb(a2 - bff(ah));
    float bden = 1.f + a2;
    unsigned short bh = bfb(bden), bl = bfb(bden - bff(bh));
    unsigned short one = bfb(1.f), zz = 0;

    // A_den (row K=16): [-2hx,-2hy,-2hz,-2lx,-2ly,-2lz,-2hx,-2hy,-2hz,ah,al,1,1,0,0,0]
    u32* A = &g_FAd[8 * p];
    A[0] = pk(m2hx, m2hy); A[1] = pk(m2hz, m2lx);
    A[2] = pk(m2ly, m2lz); A[3] = pk(m2hx, m2hy);
    A[4] = pk(m2hz, ah);   A[5] = pk(al, one);
    A[6] = pk(one, zz);    A[7] = 0;

    // B_den (col K=16): [hx,hy,hz,hx,hy,hz,lx,ly,lz,1,1,bh,bl,0,0,0] -> permuted pairs
    {
        u32 B[8];
        B[0] = pk(hx, hy);  B[1] = pk(hz, hx);
        B[2] = pk(hy, hz);  B[3] = pk(lx, ly);
        B[4] = pk(lz, one); B[5] = pk(one, bh);
        B[6] = pk(bl, zz);  B[7] = 0;
        uint2* BP = &g_FBd[4 * p];
#pragma unroll
        for (int k = 0; k < 4; k++) BP[k] = make_uint2(B[k], B[k + 4]);
    }

    // ----- numerator (weight) features: w.w' = hh' + lh' + hl' -----
    unsigned short hwx = bfb(wx), hwy = bfb(wy), hwz = bfb(wz);
    unsigned short lwx = bfb(wx - bff(hwx)), lwy = bfb(wy - bff(hwy)),
                   lwz = bfb(wz - bff(hwz));

    // A_num (row): [hwx,hwy,hwz, lwx,lwy,lwz, hwx,hwy,hwz, 0,0,0,0,0,0,0]
    u32* An = &g_FAn[8 * p];
    An[0] = pk(hwx, hwy); An[1] = pk(hwz, lwx);
    An[2] = pk(lwy, lwz); An[3] = pk(hwx, hwy);
    An[4] = pk(hwz, zz);  An[5] = 0;
    An[6] = 0;            An[7] = 0;

    // B_num (col): [hwx,hwy,hwz, hwx,hwy,hwz, lwx,lwy,lwz, 0,...] -> permuted
    {
        u32 B[8];
        B[0] = pk(hwx, hwy); B[1] = pk(hwz, hwx);
        B[2] = pk(hwy, hwz); B[3] = pk(lwx, lwy);
        B[4] = pk(lwz, zz);  B[5] = 0;
        B[6] = 0;            B[7] = 0;
        uint2* BP = &g_FBn[4 * p];
#pragma unroll
        for (int k = 0; k < 4; k++) BP[k] = make_uint2(B[k], B[k + 4]);
    }
}

// ---- main kernel: 256x256 triangular tiles, dual HMMA --------------------------
__global__ __launch_bounds__(THREADS)
void mma_kernel(int T, int nBlocks, float* __restrict__ out)
{
    __shared__ uint2  sBd[G * 4];     // 8 KB: denominator B features (permuted)
    __shared__ uint2  sBn[G * 4];     // 8 KB: numerator B features (permuted)
    __shared__ double rbuf[THREADS];  // 2 KB
    __shared__ int s_last;

    const int tid = threadIdx.x;
    const int wid = tid >> 5;
    const int lid = tid & 31;
    const int gid = lid >> 2;     // groupID 0..7
    const int tig = lid & 3;      // thread-in-group 0..3

    // block -> (ti, tj) triangular
    int b = blockIdx.x, ti = 0, row = T;
    while (b >= row) { b -= row; ti++; row--; }
    const int tj = ti + b;
    const double scale = (ti == tj) ? 1.0 : 2.0;
    const int Ibase = ti * G;
    const int Jbase = tj * G;

    // stage j-tile features (uint4 vectorized)
    {
        const uint4* sd = (const uint4*)&g_FBd[Jbase * 4];
        const uint4* sn = (const uint4*)&g_FBn[Jbase * 4];
        uint4* dd = (uint4*)sBd;
        uint4* dn = (uint4*)sBn;
        for (int k = tid; k < G * 2; k += THREADS) { dd[k] = sd[k]; dn[k] = sn[k]; }
    }

    // A fragments: 2 strips of 16 rows per warp (denominator + numerator)
    u32 ad[2][4], an[2][4];
#pragma unroll
    for (int s = 0; s < 2; s++) {
        int r0 = Ibase + s * 128 + wid * 16 + gid;
        int r1 = r0 + 8;
        ad[s][0] = g_FAd[r0 * 8 + tig];
        ad[s][1] = g_FAd[r1 * 8 + tig];
        ad[s][2] = g_FAd[r0 * 8 + tig + 4];
        ad[s][3] = g_FAd[r1 * 8 + tig + 4];
        an[s][0] = g_FAn[r0 * 8 + tig];
        an[s][1] = g_FAn[r1 * 8 + tig];
        an[s][2] = g_FAn[r0 * 8 + tig + 4];
        an[s][3] = g_FAn[r1 * 8 + tig + 4];
    }
    __syncthreads();

    float acc0 = 0.f, acc1 = 0.f, acc2 = 0.f, acc3 = 0.f;

#pragma unroll 4
    for (int jt = 0; jt < G / 8; jt++) {           // 32 j-subtiles of 8 cols
        const int fidx = (jt * 8 + gid) * 4 + tig;
        const uint2 bd = sBd[fidx];                // conflict-free LDS.64
        const uint2 bn = sBn[fidx];

#pragma unroll
        for (int s = 0; s < 2; s++) {
            float c0, c1, c2, c3, e0, e1, e2, e3;
            mma_bf16(c0, c1, c2, c3, ad[s][0], ad[s][1], ad[s][2], ad[s][3],
                     bd.x, bd.y);
            mma_bf16(e0, e1, e2, e3, an[s][0], an[s][1], an[s][2], an[s][3],
                     bn.x, bn.y);
            if (s == 0) {
                acc0 = fmaf(e0, rcpf(c0), acc0);
                acc1 = fmaf(e1, rcpf(c1), acc1);
                acc2 = fmaf(e2, rcpf(c2), acc2);
                acc3 = fmaf(e3, rcpf(c3), acc3);
            } else {
                acc0 = fmaf(e0, rcpf(c0), acc0);
                acc1 = fmaf(e1, rcpf(c1), acc1);
                acc2 = fmaf(e2, rcpf(c2), acc2);
                acc3 = fmaf(e3, rcpf(c3), acc3);
            }
        }
    }

    // deterministic block reduction
    double e = ((double)acc0 + (double)acc1) + ((double)acc2 + (double)acc3);
    rbuf[tid] = e * scale;
    __syncthreads();
#pragma unroll
    for (int off = THREADS / 2; off > 0; off >>= 1) {
        if (tid < off) rbuf[tid] += rbuf[tid + off];
        __syncthreads();
    }
    if (tid == 0) {
        g_partials[blockIdx.x] = rbuf[0];
        __threadfence();
        unsigned int ticket = atomicAdd(&g_done, 1u);
        s_last = (ticket == (unsigned int)(nBlocks - 1)) ? 1 : 0;
    }
    __syncthreads();

    // last block: fixed-order deterministic final reduction
    if (s_last) {
        double fs = 0.0;
        for (int k = tid; k < nBlocks; k += THREADS)
            fs += g_partials[k];
        rbuf[tid] = fs;
        __syncthreads();
#pragma unroll
        for (int off = THREADS / 2; off > 0; off >>= 1) {
            if (tid < off) rbuf[tid] += rbuf[tid + off];
            __syncthreads();
        }
        if (tid == 0) {
            out[0] = (float)rbuf[0];
            g_done = 0;   // self-restore for next graph replay
        }
    }
}

// ----------------------------------------------------------------------------
extern "C" void kernel_launch(void* const* d_in, const int* in_sizes, int n_in,
                              void* d_out, int out_size)
{
    const float* verts = (const float*)d_in[0];   // src_vertices  (V,3)
    const float* tnorm = (const float*)d_in[1];   // tar_normals   (M,3)
    const float* tcent = (const float*)d_in[2];   // tar_centers   (M,3)
    const int*   sidx  = (const int*)  d_in[3];   // src_indices   (N,3)

    const int N = in_sizes[3] / 3;
    const int M = in_sizes[1] / 3;
    const int total = N + M;
    const int total_pad = ((total + G - 1) / G) * G;
    const int T = total_pad / G;                  // 64 for 16384 points

    prep_kernel<<<(total_pad + 255) / 256, 256>>>(verts, tnorm, tcent, sidx,
                                                  N, M, total_pad);

    const int nBlocks = T * (T + 1) / 2;          // 2080
    mma_kernel<<<nBlocks, THREADS>>>(T, nBlocks, (float*)d_out);
}

// round 15
// speedup vs baseline: 1.6840x; 1.0521x over previous
#include <cuda_runtime.h>
#include <cuda_bf16.h>
#include <cstdint>

// ============================================================================
// DeformableCurrents: E = sum_{p,q} (w_p.w_q) / (1 + |c_p - c_q|^2)
// over combined src/tar set; f symmetric => triangular tiles (x2 off-diag).
//
// v15 = v14 (dual split-bf16 HMMA: denom + numerator, G=256) + batched
//   inversion in the epilogue. v14 measured 72% of the MUFU floor -> rcp
//   stream is the binding pipe. Montgomery pairing halves it:
//     rp = rcp(c0*c1); r0 = rp*c1; r1 = rp*c0     (products <= ~1600, safe)
//   MUFU/warp-iter 8 -> 4 at +6 FMUL (fma pipe at 12%, has slack).
// ============================================================================

typedef unsigned int u32;

#define THREADS 256
#define G       256          // square tile edge (points)
#define MAX_PTS 20480

__device__ u32    g_FAd[8 * MAX_PTS];   // A features, denominator
__device__ uint2  g_FBd[4 * MAX_PTS];   // B features, denominator (permuted)
__device__ u32    g_FAn[8 * MAX_PTS];   // A features, numerator (weights)
__device__ uint2  g_FBn[4 * MAX_PTS];   // B features, numerator (permuted)
__device__ double g_partials[4096];
__device__ unsigned int g_done = 0;

__device__ __forceinline__ float rcpf(float x) {
    float r; asm("rcp.approx.ftz.f32 %0, %1;" : "=f"(r) : "f"(x));
    return r;
}

// D(16x8,f32) = A(16x16,bf16) * B(16x8,bf16)
__device__ __forceinline__ void mma_bf16(
    float& c0, float& c1, float& c2, float& c3,
    u32 a0, u32 a1, u32 a2, u32 a3, u32 b0, u32 b1)
{
    float z = 0.f;
    asm volatile(
        "mma.sync.aligned.m16n8k16.row.col.f32.bf16.bf16.f32 "
        "{%0,%1,%2,%3}, {%4,%5,%6,%7}, {%8,%9}, {%10,%11,%12,%13};"
        : "=f"(c0), "=f"(c1), "=f"(c2), "=f"(c3)
        : "r"(a0), "r"(a1), "r"(a2), "r"(a3), "r"(b0), "r"(b1),
          "f"(z), "f"(z), "f"(z), "f"(z));
}

// ---- per-point geometry ------------------------------------------------------
__device__ __forceinline__ void make_point(
    int t, int N, int M,
    const float* __restrict__ verts, const float* __restrict__ tnorm,
    const float* __restrict__ tcent, const int* __restrict__ sidx,
    float& cx, float& cy, float& cz, float& a2,
    float& wx, float& wy, float& wz)
{
    cx = 0.f; cy = 0.f; cz = 0.f; wx = 0.f; wy = 0.f; wz = 0.f;
    if (t < N) {
        int i0 = sidx[3 * t + 0], i1 = sidx[3 * t + 1], i2 = sidx[3 * t + 2];
        float ax = verts[3 * i0], ay = verts[3 * i0 + 1], az = verts[3 * i0 + 2];
        float bx = verts[3 * i1], by = verts[3 * i1 + 1], bz = verts[3 * i1 + 2];
        float gx = verts[3 * i2], gy = verts[3 * i2 + 1], gz = verts[3 * i2 + 2];
        float e1x = ax - bx, e1y = ay - by, e1z = az - bz;
        float e2x = gx - bx, e2y = gy - by, e2z = gz - bz;
        wx = 0.5f * (e1y * e2z - e1z * e2y);
        wy = 0.5f * (e1z * e2x - e1x * e2z);
        wz = 0.5f * (e1x * e2y - e1y * e2x);
        cx = (ax + bx + gx) * (1.0f / 3.0f);
        cy = (ay + by + gy) * (1.0f / 3.0f);
        cz = (az + bz + gz) * (1.0f / 3.0f);
    } else if (t < N + M) {
        int j = t - N;
        cx = tcent[3 * j];  cy = tcent[3 * j + 1];  cz = tcent[3 * j + 2];
        wx = -tnorm[3 * j]; wy = -tnorm[3 * j + 1]; wz = -tnorm[3 * j + 2];
    }
    a2 = cx * cx + cy * cy + cz * cz;
}

__device__ __forceinline__ unsigned short bfb(float x) {
    __nv_bfloat16 h = __float2bfloat16(x);
    return *(unsigned short*)&h;
}
__device__ __forceinline__ float bff(unsigned short b) {
    __nv_bfloat16 h = *(__nv_bfloat16*)&b;
    return __bfloat162float(h);
}
__device__ __forceinline__ u32 pk(unsigned short lo, unsigned short hi) {
    return (u32)lo | ((u32)hi << 16);
}

// ---- prep: split-bf16 feature vectors for BOTH GEMMs ---------------------------
__global__ void prep_kernel(const float* __restrict__ verts,
                            const float* __restrict__ tnorm,
                            const float* __restrict__ tcent,
                            const int*   __restrict__ sidx,
                            int N, int M, int total_pad)
{
    int p = blockIdx.x * blockDim.x + threadIdx.x;
    if (p >= total_pad) return;
    float cx, cy, cz, a2, wx, wy, wz;
    make_point(p, N, M, verts, tnorm, tcent, sidx, cx, cy, cz, a2, wx, wy, wz);

    // ----- denominator features -----
    unsigned short hx = bfb(cx), hy = bfb(cy), hz = bfb(cz);
    float hxf = bff(hx), hyf = bff(hy), hzf = bff(hz);
    unsigned short lx = bfb(cx - hxf), ly = bfb(cy - hyf), lz = bfb(cz - hzf);
    unsigned short m2hx = bfb(-2.f * hxf), m2hy = bfb(-2.f * hyf), m2hz = bfb(-2.f * hzf);
    unsigned short m2lx = bfb(-2.f * bff(lx)), m2ly = bfb(-2.f * bff(ly)), m2lz = bfb(-2.f * bff(lz));
    unsigned short ah = bfb(a2), al = bfb(a2 - bff(ah));
    float bden = 1.f + a2;
    unsigned short bh = bfb(bden), bl = bfb(bden - bff(bh));
    unsigned short one = bfb(1.f), zz = 0;

    // A_den (row K=16): [-2hx,-2hy,-2hz,-2lx,-2ly,-2lz,-2hx,-2hy,-2hz,ah,al,1,1,0,0,0]
    u32* A = &g_FAd[8 * p];
    A[0] = pk(m2hx, m2hy); A[1] = pk(m2hz, m2lx);
    A[2] = pk(m2ly, m2lz); A[3] = pk(m2hx, m2hy);
    A[4] = pk(m2hz, ah);   A[5] = pk(al, one);
    A[6] = pk(one, zz);    A[7] = 0;

    // B_den (col K=16): [hx,hy,hz,hx,hy,hz,lx,ly,lz,1,1,bh,bl,0,0,0] -> permuted pairs
    {
        u32 B[8];
        B[0] = pk(hx, hy);  B[1] = pk(hz, hx);
        B[2] = pk(hy, hz);  B[3] = pk(lx, ly);
        B[4] = pk(lz, one); B[5] = pk(one, bh);
        B[6] = pk(bl, zz);  B[7] = 0;
        uint2* BP = &g_FBd[4 * p];
#pragma unroll
        for (int k = 0; k < 4; k++) BP[k] = make_uint2(B[k], B[k + 4]);
    }

    // ----- numerator (weight) features: w.w' = hh' + lh' + hl' -----
    unsigned short hwx = bfb(wx), hwy = bfb(wy), hwz = bfb(wz);
    unsigned short lwx = bfb(wx - bff(hwx)), lwy = bfb(wy - bff(hwy)),
                   lwz = bfb(wz - bff(hwz));

    // A_num (row): [hwx,hwy,hwz, lwx,lwy,lwz, hwx,hwy,hwz, 0,0,0,0,0,0,0]
    u32* An = &g_FAn[8 * p];
    An[0] = pk(hwx, hwy); An[1] = pk(hwz, lwx);
    An[2] = pk(lwy, lwz); An[3] = pk(hwx, hwy);
    An[4] = pk(hwz, zz);  An[5] = 0;
    An[6] = 0;            An[7] = 0;

    // B_num (col): [hwx,hwy,hwz, hwx,hwy,hwz, lwx,lwy,lwz, 0,...] -> permuted
    {
        u32 B[8];
        B[0] = pk(hwx, hwy); B[1] = pk(hwz, hwx);
        B[2] = pk(hwy, hwz); B[3] = pk(lwx, lwy);
        B[4] = pk(lwz, zz);  B[5] = 0;
        B[6] = 0;            B[7] = 0;
        uint2* BP = &g_FBn[4 * p];
#pragma unroll
        for (int k = 0; k < 4; k++) BP[k] = make_uint2(B[k], B[k + 4]);
    }
}

// ---- main kernel: 256x256 triangular tiles, dual HMMA, batched inversion -------
__global__ __launch_bounds__(THREADS)
void mma_kernel(int T, int nBlocks, float* __restrict__ out)
{
    __shared__ uint2  sBd[G * 4];     // 8 KB: denominator B features (permuted)
    __shared__ uint2  sBn[G * 4];     // 8 KB: numerator B features (permuted)
    __shared__ double rbuf[THREADS];  // 2 KB
    __shared__ int s_last;

    const int tid = threadIdx.x;
    const int wid = tid >> 5;
    const int lid = tid & 31;
    const int gid = lid >> 2;     // groupID 0..7
    const int tig = lid & 3;      // thread-in-group 0..3

    // block -> (ti, tj) triangular
    int b = blockIdx.x, ti = 0, row = T;
    while (b >= row) { b -= row; ti++; row--; }
    const int tj = ti + b;
    const double scale = (ti == tj) ? 1.0 : 2.0;
    const int Ibase = ti * G;
    const int Jbase = tj * G;

    // stage j-tile features (uint4 vectorized)
    {
        const uint4* sd = (const uint4*)&g_FBd[Jbase * 4];
        const uint4* sn = (const uint4*)&g_FBn[Jbase * 4];
        uint4* dd = (uint4*)sBd;
        uint4* dn = (uint4*)sBn;
        for (int k = tid; k < G * 2; k += THREADS) { dd[k] = sd[k]; dn[k] = sn[k]; }
    }

    // A fragments: 2 strips of 16 rows per warp (denominator + numerator)
    u32 ad[2][4], an[2][4];
#pragma unroll
    for (int s = 0; s < 2; s++) {
        int r0 = Ibase + s * 128 + wid * 16 + gid;
        int r1 = r0 + 8;
        ad[s][0] = g_FAd[r0 * 8 + tig];
        ad[s][1] = g_FAd[r1 * 8 + tig];
        ad[s][2] = g_FAd[r0 * 8 + tig + 4];
        ad[s][3] = g_FAd[r1 * 8 + tig + 4];
        an[s][0] = g_FAn[r0 * 8 + tig];
        an[s][1] = g_FAn[r1 * 8 + tig];
        an[s][2] = g_FAn[r0 * 8 + tig + 4];
        an[s][3] = g_FAn[r1 * 8 + tig + 4];
    }
    __syncthreads();

    float acc0 = 0.f, acc1 = 0.f, acc2 = 0.f, acc3 = 0.f;

#pragma unroll 4
    for (int jt = 0; jt < G / 8; jt++) {           // 32 j-subtiles of 8 cols
        const int fidx = (jt * 8 + gid) * 4 + tig;
        const uint2 bd = sBd[fidx];                // conflict-free LDS.64
        const uint2 bn = sBn[fidx];

#pragma unroll
        for (int s = 0; s < 2; s++) {
            float c0, c1, c2, c3, e0, e1, e2, e3;
            mma_bf16(c0, c1, c2, c3, ad[s][0], ad[s][1], ad[s][2], ad[s][3],
                     bd.x, bd.y);
            mma_bf16(e0, e1, e2, e3, an[s][0], an[s][1], an[s][2], an[s][3],
                     bn.x, bn.y);
            // batched inversion: 2 MUFU for 4 denominators
            float rp01 = rcpf(c0 * c1);
            float rp23 = rcpf(c2 * c3);
            acc0 = fmaf(e0, rp01 * c1, acc0);
            acc1 = fmaf(e1, rp01 * c0, acc1);
            acc2 = fmaf(e2, rp23 * c3, acc2);
            acc3 = fmaf(e3, rp23 * c2, acc3);
        }
    }

    // deterministic block reduction
    double e = ((double)acc0 + (double)acc1) + ((double)acc2 + (double)acc3);
    rbuf[tid] = e * scale;
    __syncthreads();
#pragma unroll
    for (int off = THREADS / 2; off > 0; off >>= 1) {
        if (tid < off) rbuf[tid] += rbuf[tid + off];
        __syncthreads();
    }
    if (tid == 0) {
        g_partials[blockIdx.x] = rbuf[0];
        __threadfence();
        unsigned int ticket = atomicAdd(&g_done, 1u);
        s_last = (ticket == (unsigned int)(nBlocks - 1)) ? 1 : 0;
    }
    __syncthreads();

    // last block: fixed-order deterministic final reduction
    if (s_last) {
        double fs = 0.0;
        for (int k = tid; k < nBlocks; k += THREADS)
            fs += g_partials[k];
        rbuf[tid] = fs;
        __syncthreads();
#pragma unroll
        for (int off = THREADS / 2; off > 0; off >>= 1) {
            if (tid < off) rbuf[tid] += rbuf[tid + off];
            __syncthreads();
        }
        if (tid == 0) {
            out[0] = (float)rbuf[0];
            g_done = 0;   // self-restore for next graph replay
        }
    }
}

// ----------------------------------------------------------------------------
extern "C" void kernel_launch(void* const* d_in, const int* in_sizes, int n_in,
                              void* d_out, int out_size)
{
    const float* verts = (const float*)d_in[0];   // src_vertices  (V,3)
    const float* tnorm = (const float*)d_in[1];   // tar_normals   (M,3)
    const float* tcent = (const float*)d_in[2];   // tar_centers   (M,3)
    const int*   sidx  = (const int*)  d_in[3];   // src_indices   (N,3)

    const int N = in_sizes[3] / 3;
    const int M = in_sizes[1] / 3;
    const int total = N + M;
    const int total_pad = ((total + G - 1) / G) * G;
    const int T = total_pad / G;                  // 64 for 16384 points

    prep_kernel<<<(total_pad + 255) / 256, 256>>>(verts, tnorm, tcent, sidx,
                                                  N, M, total_pad);

    const int nBlocks = T * (T + 1) / 2;          // 2080
    mma_kernel<<<nBlocks, THREADS>>>(T, nBlocks, (float*)d_out);
}

// round 16
// speedup vs baseline: 1.8465x; 1.0965x over previous
#include <cuda_runtime.h>
#include <cuda_bf16.h>
#include <cstdint>

// ============================================================================
// DeformableCurrents: E = sum_{p,q} (w_p.w_q) / (1 + |c_p - c_q|^2)
// over combined src/tar set; f symmetric => triangular tiles (x2 off-diag).
//
// v16 = v15 (dual split-bf16 HMMA + batched inversion, G=256) with issue cuts:
//   - B features for denom+numerator INTERLEAVED in one uint4 -> single
//     LDS.128 per j-subtile (was 2x LDS.64 + extra address math)
//   - deterministic warp-shuffle block reduction (replaces 8-sync smem tree)
//   - unroll 8
// ============================================================================

typedef unsigned int u32;

#define THREADS 256
#define G       256          // square tile edge (points)
#define MAX_PTS 20480

__device__ u32    g_FAd[8 * MAX_PTS];   // A features, denominator
__device__ u32    g_FAn[8 * MAX_PTS];   // A features, numerator (weights)
__device__ uint4  g_FBi[4 * MAX_PTS];   // B features interleaved {bd0,bd1,bn0,bn1}
__device__ double g_partials[4096];
__device__ unsigned int g_done = 0;

__device__ __forceinline__ float rcpf(float x) {
    float r; asm("rcp.approx.ftz.f32 %0, %1;" : "=f"(r) : "f"(x));
    return r;
}

// D(16x8,f32) = A(16x16,bf16) * B(16x8,bf16)
__device__ __forceinline__ void mma_bf16(
    float& c0, float& c1, float& c2, float& c3,
    u32 a0, u32 a1, u32 a2, u32 a3, u32 b0, u32 b1)
{
    float z = 0.f;
    asm volatile(
        "mma.sync.aligned.m16n8k16.row.col.f32.bf16.bf16.f32 "
        "{%0,%1,%2,%3}, {%4,%5,%6,%7}, {%8,%9}, {%10,%11,%12,%13};"
        : "=f"(c0), "=f"(c1), "=f"(c2), "=f"(c3)
        : "r"(a0), "r"(a1), "r"(a2), "r"(a3), "r"(b0), "r"(b1),
          "f"(z), "f"(z), "f"(z), "f"(z));
}

// ---- per-point geometry ------------------------------------------------------
__device__ __forceinline__ void make_point(
    int t, int N, int M,
    const float* __restrict__ verts, const float* __restrict__ tnorm,
    const float* __restrict__ tcent, const int* __restrict__ sidx,
    float& cx, float& cy, float& cz, float& a2,
    float& wx, float& wy, float& wz)
{
    cx = 0.f; cy = 0.f; cz = 0.f; wx = 0.f; wy = 0.f; wz = 0.f;
    if (t < N) {
        int i0 = sidx[3 * t + 0], i1 = sidx[3 * t + 1], i2 = sidx[3 * t + 2];
        float ax = verts[3 * i0], ay = verts[3 * i0 + 1], az = verts[3 * i0 + 2];
        float bx = verts[3 * i1], by = verts[3 * i1 + 1], bz = verts[3 * i1 + 2];
        float gx = verts[3 * i2], gy = verts[3 * i2 + 1], gz = verts[3 * i2 + 2];
        float e1x = ax - bx, e1y = ay - by, e1z = az - bz;
        float e2x = gx - bx, e2y = gy - by, e2z = gz - bz;
        wx = 0.5f * (e1y * e2z - e1z * e2y);
        wy = 0.5f * (e1z * e2x - e1x * e2z);
        wz = 0.5f * (e1x * e2y - e1y * e2x);
        cx = (ax + bx + gx) * (1.0f / 3.0f);
        cy = (ay + by + gy) * (1.0f / 3.0f);
        cz = (az + bz + gz) * (1.0f / 3.0f);
    } else if (t < N + M) {
        int j = t - N;
        cx = tcent[3 * j];  cy = tcent[3 * j + 1];  cz = tcent[3 * j + 2];
        wx = -tnorm[3 * j]; wy = -tnorm[3 * j + 1]; wz = -tnorm[3 * j + 2];
    }
    a2 = cx * cx + cy * cy + cz * cz;
}

__device__ __forceinline__ unsigned short bfb(float x) {
    __nv_bfloat16 h = __float2bfloat16(x);
    return *(unsigned short*)&h;
}
__device__ __forceinline__ float bff(unsigned short b) {
    __nv_bfloat16 h = *(__nv_bfloat16*)&b;
    return __bfloat162float(h);
}
__device__ __forceinline__ u32 pk(unsigned short lo, unsigned short hi) {
    return (u32)lo | ((u32)hi << 16);
}

// ---- prep: split-bf16 feature vectors for BOTH GEMMs ---------------------------
__global__ void prep_kernel(const float* __restrict__ verts,
                            const float* __restrict__ tnorm,
                            const float* __restrict__ tcent,
                            const int*   __restrict__ sidx,
                            int N, int M, int total_pad)
{
    int p = blockIdx.x * blockDim.x + threadIdx.x;
    if (p >= total_pad) return;
    float cx, cy, cz, a2, wx, wy, wz;
    make_point(p, N, M, verts, tnorm, tcent, sidx, cx, cy, cz, a2, wx, wy, wz);

    // ----- denominator features -----
    unsigned short hx = bfb(cx), hy = bfb(cy), hz = bfb(cz);
    float hxf = bff(hx), hyf = bff(hy), hzf = bff(hz);
    unsigned short lx = bfb(cx - hxf), ly = bfb(cy - hyf), lz = bfb(cz - hzf);
    unsigned short m2hx = bfb(-2.f * hxf), m2hy = bfb(-2.f * hyf), m2hz = bfb(-2.f * hzf);
    unsigned short m2lx = bfb(-2.f * bff(lx)), m2ly = bfb(-2.f * bff(ly)), m2lz = bfb(-2.f * bff(lz));
    unsigned short ah = bfb(a2), al = bfb(a2 - bff(ah));
    float bden = 1.f + a2;
    unsigned short bh = bfb(bden), bl = bfb(bden - bff(bh));
    unsigned short one = bfb(1.f), zz = 0;

    // A_den (row K=16): [-2hx,-2hy,-2hz,-2lx,-2ly,-2lz,-2hx,-2hy,-2hz,ah,al,1,1,0,0,0]
    u32* A = &g_FAd[8 * p];
    A[0] = pk(m2hx, m2hy); A[1] = pk(m2hz, m2lx);
    A[2] = pk(m2ly, m2lz); A[3] = pk(m2hx, m2hy);
    A[4] = pk(m2hz, ah);   A[5] = pk(al, one);
    A[6] = pk(one, zz);    A[7] = 0;

    // ----- numerator (weight) features: w.w' = hh' + lh' + hl' -----
    unsigned short hwx = bfb(wx), hwy = bfb(wy), hwz = bfb(wz);
    unsigned short lwx = bfb(wx - bff(hwx)), lwy = bfb(wy - bff(hwy)),
                   lwz = bfb(wz - bff(hwz));

    // A_num (row): [hwx,hwy,hwz, lwx,lwy,lwz, hwx,hwy,hwz, 0,0,0,0,0,0,0]
    u32* An = &g_FAn[8 * p];
    An[0] = pk(hwx, hwy); An[1] = pk(hwz, lwx);
    An[2] = pk(lwy, lwz); An[3] = pk(hwx, hwy);
    An[4] = pk(hwz, zz);  An[5] = 0;
    An[6] = 0;            An[7] = 0;

    // B features (col K=16), interleaved {bd_k, bd_{k+4}, bn_k, bn_{k+4}}
    {
        u32 Bd[8], Bn[8];
        Bd[0] = pk(hx, hy);  Bd[1] = pk(hz, hx);
        Bd[2] = pk(hy, hz);  Bd[3] = pk(lx, ly);
        Bd[4] = pk(lz, one); Bd[5] = pk(one, bh);
        Bd[6] = pk(bl, zz);  Bd[7] = 0;
        Bn[0] = pk(hwx, hwy); Bn[1] = pk(hwz, hwx);
        Bn[2] = pk(hwy, hwz); Bn[3] = pk(lwx, lwy);
        Bn[4] = pk(lwz, zz);  Bn[5] = 0;
        Bn[6] = 0;            Bn[7] = 0;
        uint4* BP = &g_FBi[4 * p];
#pragma unroll
        for (int k = 0; k < 4; k++)
            BP[k] = make_uint4(Bd[k], Bd[k + 4], Bn[k], Bn[k + 4]);
    }
}

// ---- main kernel: 256x256 triangular tiles, dual HMMA, batched inversion -------
__global__ __launch_bounds__(THREADS)
void mma_kernel(int T, int nBlocks, float* __restrict__ out)
{
    __shared__ uint4  sB[G * 4];      // 16 KB: interleaved B features
    __shared__ double swsum[8];       // per-warp partials
    __shared__ int s_last;

    const int tid = threadIdx.x;
    const int wid = tid >> 5;
    const int lid = tid & 31;
    const int gid = lid >> 2;     // groupID 0..7
    const int tig = lid & 3;      // thread-in-group 0..3

    // block -> (ti, tj) triangular
    int b = blockIdx.x, ti = 0, row = T;
    while (b >= row) { b -= row; ti++; row--; }
    const int tj = ti + b;
    const double scale = (ti == tj) ? 1.0 : 2.0;
    const int Ibase = ti * G;
    const int Jbase = tj * G;

    // stage j-tile features (uint4 vectorized)
    {
        const uint4* src = (const uint4*)&g_FBi[Jbase * 4];
        for (int k = tid; k < G * 4; k += THREADS) sB[k] = src[k];
    }

    // A fragments: 2 strips of 16 rows per warp (denominator + numerator)
    u32 ad[2][4], an[2][4];
#pragma unroll
    for (int s = 0; s < 2; s++) {
        int r0 = Ibase + s * 128 + wid * 16 + gid;
        int r1 = r0 + 8;
        ad[s][0] = g_FAd[r0 * 8 + tig];
        ad[s][1] = g_FAd[r1 * 8 + tig];
        ad[s][2] = g_FAd[r0 * 8 + tig + 4];
        ad[s][3] = g_FAd[r1 * 8 + tig + 4];
        an[s][0] = g_FAn[r0 * 8 + tig];
        an[s][1] = g_FAn[r1 * 8 + tig];
        an[s][2] = g_FAn[r0 * 8 + tig + 4];
        an[s][3] = g_FAn[r1 * 8 + tig + 4];
    }
    __syncthreads();

    float acc0 = 0.f, acc1 = 0.f, acc2 = 0.f, acc3 = 0.f;

    const uint4* bptr = &sB[gid * 4 + tig];
#pragma unroll 8
    for (int jt = 0; jt < G / 8; jt++) {           // 32 j-subtiles of 8 cols
        const uint4 bf = bptr[jt * 32];            // single conflict-free LDS.128

#pragma unroll
        for (int s = 0; s < 2; s++) {
            float c0, c1, c2, c3, e0, e1, e2, e3;
            mma_bf16(c0, c1, c2, c3, ad[s][0], ad[s][1], ad[s][2], ad[s][3],
                     bf.x, bf.y);
            mma_bf16(e0, e1, e2, e3, an[s][0], an[s][1], an[s][2], an[s][3],
                     bf.z, bf.w);
            // batched inversion: 2 MUFU for 4 denominators
            float rp01 = rcpf(c0 * c1);
            float rp23 = rcpf(c2 * c3);
            acc0 = fmaf(e0, rp01 * c1, acc0);
            acc1 = fmaf(e1, rp01 * c0, acc1);
            acc2 = fmaf(e2, rp23 * c3, acc2);
            acc3 = fmaf(e3, rp23 * c2, acc3);
        }
    }

    // deterministic reduction: warp shuffle tree (fixed lanes), then warp 0
    double e = (((double)acc0 + (double)acc1) + ((double)acc2 + (double)acc3))
               * scale;
#pragma unroll
    for (int off = 16; off > 0; off >>= 1)
        e += __shfl_down_sync(0xFFFFFFFFu, e, off);
    if (lid == 0) swsum[wid] = e;
    __syncthreads();

    if (wid == 0) {
        double v = (lid < 8) ? swsum[lid] : 0.0;
#pragma unroll
        for (int off = 4; off > 0; off >>= 1)
            v += __shfl_down_sync(0xFFFFFFFFu, v, off);
        if (lid == 0) {
            g_partials[blockIdx.x] = v;
            __threadfence();
            unsigned int ticket = atomicAdd(&g_done, 1u);
            s_last = (ticket == (unsigned int)(nBlocks - 1)) ? 1 : 0;
        }
    }
    __syncthreads();

    // last block: fixed-order deterministic final reduction
    if (s_last) {
        __shared__ double rbuf[THREADS];
        double fs = 0.0;
        for (int k = tid; k < nBlocks; k += THREADS)
            fs += g_partials[k];
        rbuf[tid] = fs;
        __syncthreads();
#pragma unroll
        for (int off = THREADS / 2; off > 0; off >>= 1) {
            if (tid < off) rbuf[tid] += rbuf[tid + off];
            __syncthreads();
        }
        if (tid == 0) {
            out[0] = (float)rbuf[0];
            g_done = 0;   // self-restore for next graph replay
        }
    }
}

// ----------------------------------------------------------------------------
extern "C" void kernel_launch(void* const* d_in, const int* in_sizes, int n_in,
                              void* d_out, int out_size)
{
    const float* verts = (const float*)d_in[0];   // src_vertices  (V,3)
    const float* tnorm = (const float*)d_in[1];   // tar_normals   (M,3)
    const float* tcent = (const float*)d_in[2];   // tar_centers   (M,3)
    const int*   sidx  = (const int*)  d_in[3];   // src_indices   (N,3)

    const int N = in_sizes[3] / 3;
    const int M = in_sizes[1] / 3;
    const int total = N + M;
    const int total_pad = ((total + G - 1) / G) * G;
    const int T = total_pad / G;                  // 64 for 16384 points

    prep_kernel<<<(total_pad + 255) / 256, 256>>>(verts, tnorm, tcent, sidx,
                                                  N, M, total_pad);

    const int nBlocks = T * (T + 1) / 2;          // 2080
    mma_kernel<<<nBlocks, THREADS>>>(T, nBlocks, (float*)d_out);
}